// round 4
// baseline (speedup 1.0000x reference)
#include <cuda_runtime.h>

#define VCAP 10240
#define NCH  40          // y-chunks
#define CHMAX 256
#define XPT  8           // x-points per thread
#define XPB  2048        // x-points per block

__device__ float    g_vni [VCAP*3];
__device__ float    g_vnn [VCAP*3];
__device__ float    g_Lv  [VCAP*3];
__device__ float    g_rs  [VCAP];
__device__ unsigned g_min [3*VCAP];   // monotone-encoded: 0 == +inf sentinel
__device__ double   g_acc [12];
__device__ unsigned g_done;

typedef unsigned long long ull;

__device__ __forceinline__ ull pack2(float lo, float hi){
  ull r; asm("mov.b64 %0, {%1, %2};" : "=l"(r) : "f"(lo), "f"(hi)); return r;
}
__device__ __forceinline__ void unpack2(ull v, float& lo, float& hi){
  asm("mov.b64 {%0, %1}, %2;" : "=f"(lo), "=f"(hi) : "l"(v));
}
__device__ __forceinline__ ull fma2(ull a, ull b, ull c){
  ull r; asm("fma.rn.f32x2 %0, %1, %2, %3;" : "=l"(r) : "l"(a), "l"(b), "l"(c)); return r;
}
__device__ __forceinline__ ull add2(ull a, ull b){
  ull r; asm("add.rn.f32x2 %0, %1, %2;" : "=l"(r) : "l"(a), "l"(b)); return r;
}

struct F3 { float x, y, z; };
__device__ __forceinline__ F3 ld3(const float* p, int i){ F3 r; r.x=p[3*i]; r.y=p[3*i+1]; r.z=p[3*i+2]; return r; }
__device__ __forceinline__ F3 sub3(F3 a, F3 b){ F3 r; r.x=a.x-b.x; r.y=a.y-b.y; r.z=a.z-b.z; return r; }
__device__ __forceinline__ F3 cross3(F3 a, F3 b){
  F3 r; r.x=a.y*b.z-a.z*b.y; r.y=a.z*b.x-a.x*b.z; r.z=a.x*b.y-a.y*b.x; return r;
}
__device__ __forceinline__ float dot3(F3 a, F3 b){ return a.x*b.x + a.y*b.y + a.z*b.z; }
__device__ __forceinline__ float len3(F3 a){ return sqrtf(dot3(a,a)); }
__device__ __forceinline__ F3 newv(const float* v, const float* d, int i){
  F3 r; r.x=v[3*i]+d[3*i]; r.y=v[3*i+1]+d[3*i+1]; r.z=v[3*i+2]+d[3*i+2]; return r;
}

// monotone encode: larger distance -> smaller key; key 0 == +inf
__device__ __forceinline__ unsigned enc_min(float d){ return 0x7f800000u - __float_as_uint(d); }
__device__ __forceinline__ float dec_min(unsigned k){ return __uint_as_float(0x7f800000u - k); }

// ---------------------------------------------------------------------------
// k_main grid layout:
//   [0, CBA)        : fused A/B chamfer tiles  (X=new_v rows, Y=trg cols)
//                       row-min -> g_min[0] (new->trg), col-min -> g_min[1] (trg->new)
//   [CBA, 2*CBA)    : symmetry tiles (X=new_v, Y=flip(new_v)); lower-triangle only,
//                       row+col mins -> g_min[2]. Upper tiles early-exit.
//   [2*CBA, +FB)    : face + interior-edge terms.
// Distances carry |x|^2 folded in (true squared distances), clamped >= 0.
// Invariants at entry (static zero init; k_vert restores every replay):
// g_vni/g_vnn/g_Lv/g_rs == 0, g_min == 0 (== +inf), g_acc == 0, g_done == 0.
// ---------------------------------------------------------------------------
__global__ void __launch_bounds__(256, 3) k_main(
    const float* __restrict__ verts, const float* __restrict__ deform,
    const float* __restrict__ trg,   const int* __restrict__ faces,
    const int* __restrict__ ev,      const int* __restrict__ eo,
    int V, int F, int E, int CBA, int XB, int CH)
{
  __shared__ __align__(16) ull sY[CHMAX*4];
  __shared__ unsigned sCol[CHMAX];
  __shared__ float sAcc[8];
  int bid = blockIdx.x;
  int tid = threadIdx.x;

  if (bid >= 2*CBA){
    // ---------------- face + edge blocks ----------------
    if (tid < 8) sAcc[tid] = 0.f;
    __syncthreads();
    int f = (bid - 2*CBA)*256 + tid;
    float el = 0.f, sm = 0.f, nc = 0.f;
    if (f < F){
      int i0 = faces[3*f], i1 = faces[3*f+1], i2 = faces[3*f+2];

      F3 v0 = ld3(verts, i0), v1 = ld3(verts, i1), v2 = ld3(verts, i2);
      F3 n = cross3(sub3(v1, v0), sub3(v2, v0));
      atomicAdd(&g_vni[3*i0+0], n.x); atomicAdd(&g_vni[3*i0+1], n.y); atomicAdd(&g_vni[3*i0+2], n.z);
      atomicAdd(&g_vni[3*i1+0], n.x); atomicAdd(&g_vni[3*i1+1], n.y); atomicAdd(&g_vni[3*i1+2], n.z);
      atomicAdd(&g_vni[3*i2+0], n.x); atomicAdd(&g_vni[3*i2+1], n.y); atomicAdd(&g_vni[3*i2+2], n.z);

      F3 d0 = ld3(deform, i0), d1 = ld3(deform, i1), d2 = ld3(deform, i2);
      F3 w0, w1, w2;
      w0.x=v0.x+d0.x; w0.y=v0.y+d0.y; w0.z=v0.z+d0.z;
      w1.x=v1.x+d1.x; w1.y=v1.y+d1.y; w1.z=v1.z+d1.z;
      w2.x=v2.x+d2.x; w2.y=v2.y+d2.y; w2.z=v2.z+d2.z;
      F3 m = cross3(sub3(w1, w0), sub3(w2, w0));
      atomicAdd(&g_vnn[3*i0+0], m.x); atomicAdd(&g_vnn[3*i0+1], m.y); atomicAdd(&g_vnn[3*i0+2], m.z);
      atomicAdd(&g_vnn[3*i1+0], m.x); atomicAdd(&g_vnn[3*i1+1], m.y); atomicAdd(&g_vnn[3*i1+2], m.z);
      atomicAdd(&g_vnn[3*i2+0], m.x); atomicAdd(&g_vnn[3*i2+1], m.y); atomicAdd(&g_vnn[3*i2+2], m.z);

      float e0 = len3(sub3(w0, w1));
      float e1 = len3(sub3(w1, w2));
      float e2 = len3(sub3(w2, w0));
      el = (e0-e1)*(e0-e1) + (e1-e2)*(e1-e2) + (e2-e0)*(e2-e0);

      sm  = fabsf(d0.x-d1.x) + fabsf(d0.y-d1.y) + fabsf(d0.z-d1.z);
      sm += fabsf(d1.x-d2.x) + fabsf(d1.y-d2.y) + fabsf(d1.z-d2.z);
      sm += fabsf(d2.x-d0.x) + fabsf(d2.y-d0.y) + fabsf(d2.z-d0.z);

      float a = e1, b = e2, c = e0;
      float s = 0.5f * (a + b + c);
      float area = sqrtf(fmaxf(s*(s-a)*(s-b)*(s-c), 1e-12f));
      float inv4a = 0.25f / area;
      float a2=a*a, b2=b*b, c2=c*c;
      float c0w = (b2 + c2 - a2) * inv4a;
      float c1w = (a2 + c2 - b2) * inv4a;
      float c2w = (a2 + b2 - c2) * inv4a;

      atomicAdd(&g_Lv[3*i1+0], c0w*w2.x); atomicAdd(&g_Lv[3*i1+1], c0w*w2.y); atomicAdd(&g_Lv[3*i1+2], c0w*w2.z);
      atomicAdd(&g_Lv[3*i2+0], c0w*w1.x); atomicAdd(&g_Lv[3*i2+1], c0w*w1.y); atomicAdd(&g_Lv[3*i2+2], c0w*w1.z);
      atomicAdd(&g_rs[i1], c0w); atomicAdd(&g_rs[i2], c0w);

      atomicAdd(&g_Lv[3*i2+0], c1w*w0.x); atomicAdd(&g_Lv[3*i2+1], c1w*w0.y); atomicAdd(&g_Lv[3*i2+2], c1w*w0.z);
      atomicAdd(&g_Lv[3*i0+0], c1w*w2.x); atomicAdd(&g_Lv[3*i0+1], c1w*w2.y); atomicAdd(&g_Lv[3*i0+2], c1w*w2.z);
      atomicAdd(&g_rs[i2], c1w); atomicAdd(&g_rs[i0], c1w);

      atomicAdd(&g_Lv[3*i0+0], c2w*w1.x); atomicAdd(&g_Lv[3*i0+1], c2w*w1.y); atomicAdd(&g_Lv[3*i0+2], c2w*w1.z);
      atomicAdd(&g_Lv[3*i1+0], c2w*w0.x); atomicAdd(&g_Lv[3*i1+1], c2w*w0.y); atomicAdd(&g_Lv[3*i1+2], c2w*w0.z);
      atomicAdd(&g_rs[i0], c2w); atomicAdd(&g_rs[i1], c2w);
    }
    if (f < E){
      int a = ev[2*f], b = ev[2*f+1], o0 = eo[2*f], o1 = eo[2*f+1];
      F3 va = newv(verts, deform, a),  vb = newv(verts, deform, b);
      F3 p0 = newv(verts, deform, o0), p1 = newv(verts, deform, o1);
      F3 edg = sub3(vb, va);
      F3 n0 = cross3(edg, sub3(p0, va));
      F3 n1 = cross3(edg, sub3(p1, va));
      n1.x = -n1.x; n1.y = -n1.y; n1.z = -n1.z;
      float dt = dot3(n0, n1);
      float dn = sqrtf(dot3(n0,n0)) * sqrtf(dot3(n1,n1));
      nc = 1.0f - dt / fmaxf(dn, 1e-8f);
    }
    float vals[3] = {el, sm, nc};
    #pragma unroll
    for (int s = 0; s < 3; s++){
      float v = vals[s];
      #pragma unroll
      for (int o = 16; o; o >>= 1) v += __shfl_xor_sync(0xffffffffu, v, o);
      if ((tid & 31) == 0) atomicAdd(&sAcc[s], v);
    }
    __syncthreads();
    if (tid == 0){
      atomicAdd(&g_acc[0], (double)sAcc[0]);
      atomicAdd(&g_acc[1], (double)sAcc[1]);
      atomicAdd(&g_acc[2], (double)sAcc[2]);
    }
    return;
  }

  // ---------------- fused chamfer tiles ----------------
  int mode  = (bid < CBA) ? 0 : 1;        // 0: A/B vs trg, 1: symmetry
  int t     = (mode == 0) ? bid : bid - CBA;
  int xblk  = t % XB;
  int chunk = t / XB;

  int y0  = chunk * CH;
  int cnt = V - y0; if (cnt > CH) cnt = CH; if (cnt < 0) cnt = 0;

  if (mode == 1){
    int xmax = xblk*XPB + XPB - 1; if (xmax > V-1) xmax = V-1;
    if (xmax < y0) return;               // strictly upper-triangle tile: skip
  }

  for (int j = tid; j < cnt; j += 256){
    int yi = y0 + j;
    float yx, yy, yz;
    if (mode == 0){
      yx = trg[3*yi]; yy = trg[3*yi+1]; yz = trg[3*yi+2];
    } else {
      yx = -(verts[3*yi]   + deform[3*yi]);
      yy =   verts[3*yi+1] + deform[3*yi+1];
      yz =   verts[3*yi+2] + deform[3*yi+2];
    }
    float q = yx*yx + yy*yy + yz*yz;
    sY[j*4+0] = pack2(-2.f*yx, -2.f*yx);
    sY[j*4+1] = pack2(-2.f*yy, -2.f*yy);
    sY[j*4+2] = pack2(-2.f*yz, -2.f*yz);
    sY[j*4+3] = pack2(q, q);
  }
  for (int j = tid; j < cnt; j += 256) sCol[j] = 0x7f800000u;
  __syncthreads();

  int base = xblk*XPB + tid;
  float xs[XPT][3];
  #pragma unroll
  for (int k = 0; k < XPT; k++){
    int idx = base + 256*k; if (idx >= V) idx = V-1;
    xs[k][0] = verts[3*idx]   + deform[3*idx];     // X is always new_v
    xs[k][1] = verts[3*idx+1] + deform[3*idx+1];
    xs[k][2] = verts[3*idx+2] + deform[3*idx+2];
  }
  ull Xx[XPT/2], Xy[XPT/2], Xz[XPT/2], Qp[XPT/2];
  #pragma unroll
  for (int p = 0; p < XPT/2; p++){
    Xx[p] = pack2(xs[2*p][0], xs[2*p+1][0]);
    Xy[p] = pack2(xs[2*p][1], xs[2*p+1][1]);
    Xz[p] = pack2(xs[2*p][2], xs[2*p+1][2]);
    float q0 = xs[2*p][0]*xs[2*p][0] + xs[2*p][1]*xs[2*p][1] + xs[2*p][2]*xs[2*p][2];
    float q1 = xs[2*p+1][0]*xs[2*p+1][0] + xs[2*p+1][1]*xs[2*p+1][1] + xs[2*p+1][2]*xs[2*p+1][2];
    Qp[p] = pack2(q0, q1);
  }
  float m[XPT];
  #pragma unroll
  for (int k = 0; k < XPT; k++) m[k] = __int_as_float(0x7f800000);

  const ulonglong2* sp = (const ulonglong2*)sY;
  for (int j = 0; j < cnt; j++){
    ulonglong2 A  = sp[2*j];      // (-2yx | -2yy)
    ulonglong2 Bv = sp[2*j+1];    // (-2yz | qy)
    float lo[XPT/2], hi[XPT/2];
    #pragma unroll
    for (int p = 0; p < XPT/2; p++){
      ull v = fma2(Xx[p], A.x, Qp[p]);
      v = fma2(Xy[p], A.y, v);
      v = fma2(Xz[p], Bv.x, v);
      v = add2(v, Bv.y);                       // true squared distance (2 lanes)
      unpack2(v, lo[p], hi[p]);
      m[2*p]   = fminf(m[2*p],   lo[p]);
      m[2*p+1] = fminf(m[2*p+1], hi[p]);
    }
    // column (y) min across this thread's 8 x-points, then warp, then block
    float c = fminf(fminf(fminf(lo[0], hi[0]), fminf(lo[1], hi[1])),
                    fminf(fminf(lo[2], hi[2]), fminf(lo[3], hi[3])));
    #pragma unroll
    for (int o = 16; o; o >>= 1) c = fminf(c, __shfl_xor_sync(0xffffffffu, c, o));
    if ((tid & 31) == 0) atomicMin(&sCol[j], __float_as_uint(c));
  }

  unsigned* gRow = (mode == 0) ? (g_min)        : (g_min + 2*VCAP);
  unsigned* gCol = (mode == 0) ? (g_min + VCAP) : (g_min + 2*VCAP);
  #pragma unroll
  for (int k = 0; k < XPT; k++){
    int idx = base + 256*k;
    if (idx < V) atomicMax(&gRow[idx], enc_min(fmaxf(m[k], 0.f)));
  }
  __syncthreads();
  for (int j = tid; j < cnt; j += 256){
    float d = fmaxf(__uint_as_float(sCol[j]), 0.f);
    atomicMax(&gCol[y0 + j], enc_min(d));
  }
}

// ---------------------------------------------------------------------------
// k_vert: decode per-vertex chamfer mins; vertex-normal consistency,
// penetration, laplacian norm; reset all scratch; last block combines.
// ---------------------------------------------------------------------------
__global__ void __launch_bounds__(256) k_vert(
    const float* __restrict__ verts, const float* __restrict__ deform,
    const float* __restrict__ trg, float* __restrict__ out,
    int V, int F, int E)
{
  __shared__ float sAcc[8];
  int tid = threadIdx.x;
  if (tid < 8) sAcc[tid] = 0.f;
  __syncthreads();

  int i = blockIdx.x*blockDim.x + tid;
  float chA=0.f, chB=0.f, chS=0.f, cons=0.f, pen=0.f, lap=0.f;
  if (i < V){
    chA = dec_min(g_min[0*VCAP + i]);
    chB = dec_min(g_min[1*VCAP + i]);
    chS = dec_min(g_min[2*VCAP + i]);
    g_min[0*VCAP + i] = 0u; g_min[1*VCAP + i] = 0u; g_min[2*VCAP + i] = 0u;

    F3 nv = newv(verts, deform, i);

    F3 a = ld3(g_vni, i);
    float ia = 1.0f / fmaxf(sqrtf(dot3(a,a)), 1e-6f);
    F3 ni; ni.x = a.x*ia; ni.y = a.y*ia; ni.z = a.z*ia;

    F3 b = ld3(g_vnn, i);
    float ib = 1.0f / fmaxf(sqrtf(dot3(b,b)), 1e-6f);
    float dx = b.x*ib - ni.x, dy = b.y*ib - ni.y, dz = b.z*ib - ni.z;
    cons = dx*dx + dy*dy + dz*dz;

    F3 df = ld3(deform, i);
    pen = fmaxf(-dot3(df, ni), 0.f);

    float r = g_rs[i];
    float inv = (r > 0.f) ? (1.0f / r) : 0.f;
    F3 lv = ld3(g_Lv, i);
    float ex = lv.x*inv - nv.x, ey = lv.y*inv - nv.y, ez = lv.z*inv - nv.z;
    lap = sqrtf(ex*ex + ey*ey + ez*ez);

    g_vni[3*i]=0.f; g_vni[3*i+1]=0.f; g_vni[3*i+2]=0.f;
    g_vnn[3*i]=0.f; g_vnn[3*i+1]=0.f; g_vnn[3*i+2]=0.f;
    g_Lv [3*i]=0.f; g_Lv [3*i+1]=0.f; g_Lv [3*i+2]=0.f;
    g_rs[i] = 0.f;
  }
  float vals[6] = {chA, chB, chS, cons, pen, lap};
  #pragma unroll
  for (int s = 0; s < 6; s++){
    float v = vals[s];
    #pragma unroll
    for (int o = 16; o; o >>= 1) v += __shfl_xor_sync(0xffffffffu, v, o);
    if ((tid & 31) == 0) atomicAdd(&sAcc[s], v);
  }
  __syncthreads();
  if (tid == 0){
    atomicAdd(&g_acc[6], (double)sAcc[0]);   // chamfer A
    atomicAdd(&g_acc[7], (double)sAcc[1]);   // chamfer B
    atomicAdd(&g_acc[8], (double)sAcc[2]);   // symmetry
    atomicAdd(&g_acc[4], (double)sAcc[3]);   // consistency
    atomicAdd(&g_acc[5], (double)sAcc[4]);   // penetration
    atomicAdd(&g_acc[3], (double)sAcc[5]);   // laplacian
    __threadfence();
    unsigned t = atomicAdd(&g_done, 1u);
    if (t == gridDim.x - 1){
      g_done = 0;
      double dV = (double)V, dF = (double)F, dE = (double)E;
      double loss = (g_acc[6] + g_acc[7]) / dV;      // chamfer
      loss += 0.1 * (g_acc[0] / dF);                 // edge
      loss += 0.1 * (g_acc[2] / dE);                 // normal consistency
      loss += 0.1 * (g_acc[1] / (3.0 * dF));         // smooth
      loss += 0.1 * (g_acc[3] / dV);                 // laplacian
      loss += 0.1 * (g_acc[4] / (3.0 * dV));         // consistency
      loss += 0.1 * (2.0 * g_acc[8] / dV);           // symmetry (2x rowmin)
      loss += 0.1 * (g_acc[5] / dV);                 // penetration
      out[0] = (float)loss;
      #pragma unroll
      for (int s = 0; s < 12; s++) g_acc[s] = 0.0;
    }
  }
}

extern "C" void kernel_launch(void* const* d_in, const int* in_sizes, int n_in,
                              void* d_out, int out_size){
  const float* verts  = (const float*)d_in[0];
  const float* deform = (const float*)d_in[1];
  const float* trg    = (const float*)d_in[2];
  const int*   faces  = (const int*)d_in[3];
  const int*   ev     = (const int*)d_in[4];
  const int*   eo     = (const int*)d_in[5];
  int V = in_sizes[0] / 3;
  int F = in_sizes[3] / 3;
  int E = in_sizes[4] / 2;
  int maxFE = F > E ? F : E;
  int FB = (maxFE + 255) / 256;
  int XB = (V + XPB - 1) / XPB;
  int CH = (V + NCH - 1) / NCH;

  int CBA = XB * NCH;
  k_main<<<2*CBA + FB, 256>>>(verts, deform, trg, faces, ev, eo, V, F, E, CBA, XB, CH);
  k_vert<<<(V + 255)/256, 256>>>(verts, deform, trg, (float*)d_out, V, F, E);
}

// round 5
// speedup vs baseline: 2.1282x; 2.1282x over previous
#include <cuda_runtime.h>

#define VCAP 10240
#define NCH  51          // y-chunks per mode
#define CHMAX 256
#define XPT  8           // x-points per thread
#define XPB  2048        // x-points per block

__device__ float    g_vni [VCAP*3];
__device__ float    g_vnn [VCAP*3];
__device__ float    g_Lv  [VCAP*3];
__device__ float    g_rs  [VCAP];
__device__ unsigned g_min [3*VCAP];   // monotone-encoded; 0 == +inf sentinel
__device__ double   g_acc [12];
__device__ unsigned g_done, g_done2;

typedef unsigned long long ull;

__device__ __forceinline__ ull pack2(float lo, float hi){
  ull r; asm("mov.b64 %0, {%1, %2};" : "=l"(r) : "f"(lo), "f"(hi)); return r;
}
__device__ __forceinline__ void unpack2(ull v, float& lo, float& hi){
  asm("mov.b64 {%0, %1}, %2;" : "=f"(lo), "=f"(hi) : "l"(v));
}
__device__ __forceinline__ ull fma2(ull a, ull b, ull c){
  ull r; asm("fma.rn.f32x2 %0, %1, %2, %3;" : "=l"(r) : "l"(a), "l"(b), "l"(c)); return r;
}

struct F3 { float x, y, z; };
__device__ __forceinline__ F3 ld3(const float* p, int i){ F3 r; r.x=p[3*i]; r.y=p[3*i+1]; r.z=p[3*i+2]; return r; }
__device__ __forceinline__ F3 sub3(F3 a, F3 b){ F3 r; r.x=a.x-b.x; r.y=a.y-b.y; r.z=a.z-b.z; return r; }
__device__ __forceinline__ F3 cross3(F3 a, F3 b){
  F3 r; r.x=a.y*b.z-a.z*b.y; r.y=a.z*b.x-a.x*b.z; r.z=a.x*b.y-a.y*b.x; return r;
}
__device__ __forceinline__ float dot3(F3 a, F3 b){ return a.x*b.x + a.y*b.y + a.z*b.z; }
__device__ __forceinline__ float len3(F3 a){ return sqrtf(dot3(a,a)); }
__device__ __forceinline__ F3 newv(const float* v, const float* d, int i){
  F3 r; r.x=v[3*i]+d[3*i]; r.y=v[3*i+1]+d[3*i+1]; r.z=v[3*i+2]+d[3*i+2]; return r;
}

// monotone encode: larger distance -> smaller key; key 0 == +inf  (d must be >= 0)
__device__ __forceinline__ unsigned enc_min(float d){ return 0x7f800000u - __float_as_uint(d); }
__device__ __forceinline__ float dec_min(unsigned k){ return __uint_as_float(0x7f800000u - k); }

// ---------------------------------------------------------------------------
// ONE kernel, grid layout (bid order = dispatch order, vertex blocks last):
//   [0, FB)            : face + interior-edge terms  (workers)
//   [FB, FB+CBS)       : chamfer tiles (xblk, mode, chunk)  (workers)
//         mode 0: X=new_v, Y=trg -> g_min[0]   mode 1: X=trg, Y=new_v -> g_min[1]
//         mode 2: X=new_v, Y=flip(new_v) -> g_min[2] (symmetric matrix: 2x at combine)
//   [FB+CBS, +VB)      : vertex blocks — spin on g_done==W, then reduce + combine.
// Chamfer tiles fold |x|^2 in before the RED (true sq dist, clamped >= 0).
// Entry invariants (static zero init; vertex blocks restore them every replay):
// g_vni/g_vnn/g_Lv/g_rs == 0, g_min == 0 (== +inf), g_acc == 0, g_done(2) == 0.
// ---------------------------------------------------------------------------
__global__ void __launch_bounds__(256) k_fused(
    const float* __restrict__ verts, const float* __restrict__ deform,
    const float* __restrict__ trg,   const int* __restrict__ faces,
    const int* __restrict__ ev,      const int* __restrict__ eo,
    int V, int F, int E, int FB, int CBS, int XB, int CH, int W, int VB,
    float* __restrict__ out)
{
  __shared__ __align__(16) ull sY[CHMAX*4];
  __shared__ float sAcc[8];
  int bid = blockIdx.x;
  int tid = threadIdx.x;

  if (bid < FB){
    // ================= face + edge workers =================
    if (tid < 8) sAcc[tid] = 0.f;
    __syncthreads();
    int f = bid*256 + tid;
    float el = 0.f, sm = 0.f, nc = 0.f;
    if (f < F){
      int i0 = faces[3*f], i1 = faces[3*f+1], i2 = faces[3*f+2];

      F3 v0 = ld3(verts, i0), v1 = ld3(verts, i1), v2 = ld3(verts, i2);
      F3 n = cross3(sub3(v1, v0), sub3(v2, v0));
      atomicAdd(&g_vni[3*i0+0], n.x); atomicAdd(&g_vni[3*i0+1], n.y); atomicAdd(&g_vni[3*i0+2], n.z);
      atomicAdd(&g_vni[3*i1+0], n.x); atomicAdd(&g_vni[3*i1+1], n.y); atomicAdd(&g_vni[3*i1+2], n.z);
      atomicAdd(&g_vni[3*i2+0], n.x); atomicAdd(&g_vni[3*i2+1], n.y); atomicAdd(&g_vni[3*i2+2], n.z);

      F3 d0 = ld3(deform, i0), d1 = ld3(deform, i1), d2 = ld3(deform, i2);
      F3 w0, w1, w2;
      w0.x=v0.x+d0.x; w0.y=v0.y+d0.y; w0.z=v0.z+d0.z;
      w1.x=v1.x+d1.x; w1.y=v1.y+d1.y; w1.z=v1.z+d1.z;
      w2.x=v2.x+d2.x; w2.y=v2.y+d2.y; w2.z=v2.z+d2.z;
      F3 m = cross3(sub3(w1, w0), sub3(w2, w0));
      atomicAdd(&g_vnn[3*i0+0], m.x); atomicAdd(&g_vnn[3*i0+1], m.y); atomicAdd(&g_vnn[3*i0+2], m.z);
      atomicAdd(&g_vnn[3*i1+0], m.x); atomicAdd(&g_vnn[3*i1+1], m.y); atomicAdd(&g_vnn[3*i1+2], m.z);
      atomicAdd(&g_vnn[3*i2+0], m.x); atomicAdd(&g_vnn[3*i2+1], m.y); atomicAdd(&g_vnn[3*i2+2], m.z);

      float e0 = len3(sub3(w0, w1));
      float e1 = len3(sub3(w1, w2));
      float e2 = len3(sub3(w2, w0));
      el = (e0-e1)*(e0-e1) + (e1-e2)*(e1-e2) + (e2-e0)*(e2-e0);

      sm  = fabsf(d0.x-d1.x) + fabsf(d0.y-d1.y) + fabsf(d0.z-d1.z);
      sm += fabsf(d1.x-d2.x) + fabsf(d1.y-d2.y) + fabsf(d1.z-d2.z);
      sm += fabsf(d2.x-d0.x) + fabsf(d2.y-d0.y) + fabsf(d2.z-d0.z);

      float a = e1, b = e2, c = e0;
      float s = 0.5f * (a + b + c);
      float area = sqrtf(fmaxf(s*(s-a)*(s-b)*(s-c), 1e-12f));
      float inv4a = 0.25f / area;
      float a2=a*a, b2=b*b, c2=c*c;
      float c0w = (b2 + c2 - a2) * inv4a;
      float c1w = (a2 + c2 - b2) * inv4a;
      float c2w = (a2 + b2 - c2) * inv4a;

      atomicAdd(&g_Lv[3*i1+0], c0w*w2.x); atomicAdd(&g_Lv[3*i1+1], c0w*w2.y); atomicAdd(&g_Lv[3*i1+2], c0w*w2.z);
      atomicAdd(&g_Lv[3*i2+0], c0w*w1.x); atomicAdd(&g_Lv[3*i2+1], c0w*w1.y); atomicAdd(&g_Lv[3*i2+2], c0w*w1.z);
      atomicAdd(&g_rs[i1], c0w); atomicAdd(&g_rs[i2], c0w);

      atomicAdd(&g_Lv[3*i2+0], c1w*w0.x); atomicAdd(&g_Lv[3*i2+1], c1w*w0.y); atomicAdd(&g_Lv[3*i2+2], c1w*w0.z);
      atomicAdd(&g_Lv[3*i0+0], c1w*w2.x); atomicAdd(&g_Lv[3*i0+1], c1w*w2.y); atomicAdd(&g_Lv[3*i0+2], c1w*w2.z);
      atomicAdd(&g_rs[i2], c1w); atomicAdd(&g_rs[i0], c1w);

      atomicAdd(&g_Lv[3*i0+0], c2w*w1.x); atomicAdd(&g_Lv[3*i0+1], c2w*w1.y); atomicAdd(&g_Lv[3*i0+2], c2w*w1.z);
      atomicAdd(&g_Lv[3*i1+0], c2w*w0.x); atomicAdd(&g_Lv[3*i1+1], c2w*w0.y); atomicAdd(&g_Lv[3*i1+2], c2w*w0.z);
      atomicAdd(&g_rs[i0], c2w); atomicAdd(&g_rs[i1], c2w);
    }
    if (f < E){
      int a = ev[2*f], b = ev[2*f+1], o0 = eo[2*f], o1 = eo[2*f+1];
      F3 va = newv(verts, deform, a),  vb = newv(verts, deform, b);
      F3 p0 = newv(verts, deform, o0), p1 = newv(verts, deform, o1);
      F3 edg = sub3(vb, va);
      F3 n0 = cross3(edg, sub3(p0, va));
      F3 n1 = cross3(edg, sub3(p1, va));
      n1.x = -n1.x; n1.y = -n1.y; n1.z = -n1.z;
      float dt = dot3(n0, n1);
      float dn = sqrtf(dot3(n0,n0)) * sqrtf(dot3(n1,n1));
      nc = 1.0f - dt / fmaxf(dn, 1e-8f);
    }
    float vals[3] = {el, sm, nc};
    #pragma unroll
    for (int s = 0; s < 3; s++){
      float v = vals[s];
      #pragma unroll
      for (int o = 16; o; o >>= 1) v += __shfl_xor_sync(0xffffffffu, v, o);
      if ((tid & 31) == 0) atomicAdd(&sAcc[s], v);
    }
    __syncthreads();
    if (tid == 0){
      atomicAdd(&g_acc[0], (double)sAcc[0]);
      atomicAdd(&g_acc[1], (double)sAcc[1]);
      atomicAdd(&g_acc[2], (double)sAcc[2]);
      __threadfence();
      atomicAdd(&g_done, 1u);
    }
    return;
  }

  if (bid < FB + CBS){
    // ================= chamfer workers =================
    int t     = bid - FB;
    int xblk  = t % XB;
    int rest  = t / XB;
    int mode  = rest % 3;
    int chunk = rest / 3;

    int y0  = chunk * CH;
    int cnt = V - y0; if (cnt > CH) cnt = CH; if (cnt < 0) cnt = 0;

    for (int j = tid; j < cnt; j += 256){
      int yi = y0 + j;
      float yx, yy, yz;
      if (mode == 0){
        yx = trg[3*yi]; yy = trg[3*yi+1]; yz = trg[3*yi+2];
      } else {
        yx = verts[3*yi]   + deform[3*yi];
        yy = verts[3*yi+1] + deform[3*yi+1];
        yz = verts[3*yi+2] + deform[3*yi+2];
        if (mode == 2) yx = -yx;
      }
      float q = yx*yx + yy*yy + yz*yz;
      sY[j*4+0] = pack2(-2.f*yx, -2.f*yx);
      sY[j*4+1] = pack2(-2.f*yy, -2.f*yy);
      sY[j*4+2] = pack2(-2.f*yz, -2.f*yz);
      sY[j*4+3] = pack2(q, q);
    }
    __syncthreads();

    int base = xblk*XPB + tid;
    float xs[XPT][3], qx[XPT];
    #pragma unroll
    for (int k = 0; k < XPT; k++){
      int idx = base + 256*k; if (idx >= V) idx = V-1;
      if (mode == 1){
        xs[k][0] = trg[3*idx]; xs[k][1] = trg[3*idx+1]; xs[k][2] = trg[3*idx+2];
      } else {
        xs[k][0] = verts[3*idx]   + deform[3*idx];
        xs[k][1] = verts[3*idx+1] + deform[3*idx+1];
        xs[k][2] = verts[3*idx+2] + deform[3*idx+2];
      }
      qx[k] = xs[k][0]*xs[k][0] + xs[k][1]*xs[k][1] + xs[k][2]*xs[k][2];
    }
    ull Xx[XPT/2], Xy[XPT/2], Xz[XPT/2];
    #pragma unroll
    for (int p = 0; p < XPT/2; p++){
      Xx[p] = pack2(xs[2*p][0], xs[2*p+1][0]);
      Xy[p] = pack2(xs[2*p][1], xs[2*p+1][1]);
      Xz[p] = pack2(xs[2*p][2], xs[2*p+1][2]);
    }
    float m[XPT];
    #pragma unroll
    for (int k = 0; k < XPT; k++) m[k] = __int_as_float(0x7f800000);

    const ulonglong2* sp = (const ulonglong2*)sY;
    #pragma unroll 2
    for (int j = 0; j < cnt; j++){
      ulonglong2 A = sp[2*j];      // (-2yx | -2yy)
      ulonglong2 B = sp[2*j+1];    // (-2yz | qy)
      #pragma unroll
      for (int p = 0; p < XPT/2; p++){
        ull v = fma2(Xx[p], A.x, B.y);
        v = fma2(Xy[p], A.y, v);
        v = fma2(Xz[p], B.x, v);
        float lo, hi; unpack2(v, lo, hi);
        m[2*p]   = fminf(m[2*p],   lo);
        m[2*p+1] = fminf(m[2*p+1], hi);
      }
    }

    unsigned* gm = g_min + mode*VCAP;
    #pragma unroll
    for (int k = 0; k < XPT; k++){
      int idx = base + 256*k;
      if (idx < V){
        float d = fmaxf(m[k] + qx[k], 0.f);       // true squared distance
        atomicMax(&gm[idx], enc_min(d));
      }
    }
    __syncthreads();
    if (tid == 0){
      __threadfence();
      atomicAdd(&g_done, 1u);
    }
    return;
  }

  // ================= vertex blocks (dispatched last; gated) =================
  if (tid < 8) sAcc[tid] = 0.f;
  if (tid == 0){
    while (atomicAdd(&g_done, 0u) < (unsigned)W) __nanosleep(64);
  }
  __syncthreads();
  __threadfence();

  int i = (bid - FB - CBS)*256 + tid;
  float chA=0.f, chB=0.f, chS=0.f, cons=0.f, pen=0.f, lap=0.f;
  if (i < V){
    chA = dec_min(g_min[0*VCAP + i]);
    chB = dec_min(g_min[1*VCAP + i]);
    chS = dec_min(g_min[2*VCAP + i]);
    g_min[0*VCAP + i] = 0u; g_min[1*VCAP + i] = 0u; g_min[2*VCAP + i] = 0u;

    F3 nv = newv(verts, deform, i);

    F3 a = ld3(g_vni, i);
    float ia = 1.0f / fmaxf(sqrtf(dot3(a,a)), 1e-6f);
    F3 ni; ni.x = a.x*ia; ni.y = a.y*ia; ni.z = a.z*ia;

    F3 b = ld3(g_vnn, i);
    float ib = 1.0f / fmaxf(sqrtf(dot3(b,b)), 1e-6f);
    float dx = b.x*ib - ni.x, dy = b.y*ib - ni.y, dz = b.z*ib - ni.z;
    cons = dx*dx + dy*dy + dz*dz;

    F3 df = ld3(deform, i);
    pen = fmaxf(-dot3(df, ni), 0.f);

    float r = g_rs[i];
    float inv = (r > 0.f) ? (1.0f / r) : 0.f;
    F3 lv = ld3(g_Lv, i);
    float ex = lv.x*inv - nv.x, ey = lv.y*inv - nv.y, ez = lv.z*inv - nv.z;
    lap = sqrtf(ex*ex + ey*ey + ez*ez);

    // restore zero-invariant for the next graph replay
    g_vni[3*i]=0.f; g_vni[3*i+1]=0.f; g_vni[3*i+2]=0.f;
    g_vnn[3*i]=0.f; g_vnn[3*i+1]=0.f; g_vnn[3*i+2]=0.f;
    g_Lv [3*i]=0.f; g_Lv [3*i+1]=0.f; g_Lv [3*i+2]=0.f;
    g_rs[i] = 0.f;
  }
  float vals[6] = {chA, chB, chS, cons, pen, lap};
  #pragma unroll
  for (int s = 0; s < 6; s++){
    float v = vals[s];
    #pragma unroll
    for (int o = 16; o; o >>= 1) v += __shfl_xor_sync(0xffffffffu, v, o);
    if ((tid & 31) == 0) atomicAdd(&sAcc[s], v);
  }
  __syncthreads();
  if (tid == 0){
    atomicAdd(&g_acc[6], (double)sAcc[0]);   // chamfer A (new->trg)
    atomicAdd(&g_acc[7], (double)sAcc[1]);   // chamfer B (trg->new)
    atomicAdd(&g_acc[8], (double)sAcc[2]);   // symmetry
    atomicAdd(&g_acc[4], (double)sAcc[3]);   // consistency
    atomicAdd(&g_acc[5], (double)sAcc[4]);   // penetration
    atomicAdd(&g_acc[3], (double)sAcc[5]);   // laplacian
    __threadfence();
    unsigned t = atomicAdd(&g_done2, 1u);
    if (t == (unsigned)(VB - 1)){
      double dV = (double)V, dF = (double)F, dE = (double)E;
      double loss = (g_acc[6] + g_acc[7]) / dV;      // chamfer
      loss += 0.1 * (g_acc[0] / dF);                 // edge
      loss += 0.1 * (g_acc[2] / dE);                 // normal consistency
      loss += 0.1 * (g_acc[1] / (3.0 * dF));         // smooth
      loss += 0.1 * (g_acc[3] / dV);                 // laplacian
      loss += 0.1 * (g_acc[4] / (3.0 * dV));         // consistency
      loss += 0.1 * (2.0 * g_acc[8] / dV);           // symmetry (2x rowmin)
      loss += 0.1 * (g_acc[5] / dV);                 // penetration
      out[0] = (float)loss;
      #pragma unroll
      for (int s = 0; s < 12; s++) g_acc[s] = 0.0;
      g_done = 0u;
      g_done2 = 0u;
    }
  }
}

extern "C" void kernel_launch(void* const* d_in, const int* in_sizes, int n_in,
                              void* d_out, int out_size){
  const float* verts  = (const float*)d_in[0];
  const float* deform = (const float*)d_in[1];
  const float* trg    = (const float*)d_in[2];
  const int*   faces  = (const int*)d_in[3];
  const int*   ev     = (const int*)d_in[4];
  const int*   eo     = (const int*)d_in[5];
  int V = in_sizes[0] / 3;
  int F = in_sizes[3] / 3;
  int E = in_sizes[4] / 2;
  int maxFE = F > E ? F : E;
  int FB  = (maxFE + 255) / 256;
  int XB  = (V + XPB - 1) / XPB;
  int CH  = (V + NCH - 1) / NCH;
  int CBS = XB * 3 * NCH;
  int W   = FB + CBS;                 // worker blocks
  int VB  = (V + 255) / 256;          // vertex blocks

  k_fused<<<W + VB, 256>>>(verts, deform, trg, faces, ev, eo,
                           V, F, E, FB, CBS, XB, CH, W, VB, (float*)d_out);
}